// round 1
// baseline (speedup 1.0000x reference)
#include <cuda_runtime.h>
#include <math.h>

#define SEQ 2048
#define HIDDEN 4096
#define NH 32
#define NKV 8
#define HD 128

// ---------------- scratch (device globals; no allocations allowed) ----------
__device__ float g_q[SEQ * NH * HD];     // [S, H, D]
__device__ float g_k[SEQ * NKV * HD];    // [S, KV, D]
__device__ float g_v[SEQ * NKV * HD];    // [S, KV, D]
__device__ float g_ctx[SEQ * NH * HD];   // [S, H, D]
__device__ double g_invfreq[64];

// ---------------- rope freq table (double precision) ------------------------
__global__ void init_invfreq_kernel() {
    int i = threadIdx.x;
    if (i < 64) {
        g_invfreq[i] = exp(-((double)i) * (log(1.0e6) / 64.0));
    }
}

// ---------------- SGEMM: C[M,N] = A[M,K] * B[N,K]^T  (all row-major) --------
// M,N multiples of 128; K multiple of 16. 256 threads, 8x8 microtile.
__global__ __launch_bounds__(256) void sgemm_nt(const float* __restrict__ A,
                                                const float* __restrict__ B,
                                                float* __restrict__ C,
                                                int M, int N, int K)
{
    __shared__ float As[16 * 132];
    __shared__ float Bs[16 * 132];

    const int t  = threadIdx.x;
    const int bm = blockIdx.y * 128;
    const int bn = blockIdx.x * 128;
    const int ty = t >> 4;        // 0..15
    const int tx = t & 15;        // 0..15
    const int lr = t >> 2;        // 0..63  (load row)
    const int lk = (t & 3) << 2;  // 0,4,8,12

    const float* Ap0 = A + (size_t)(bm + lr) * K + lk;
    const float* Ap1 = A + (size_t)(bm + lr + 64) * K + lk;
    const float* Bp0 = B + (size_t)(bn + lr) * K + lk;
    const float* Bp1 = B + (size_t)(bn + lr + 64) * K + lk;

    float acc[8][8];
    #pragma unroll
    for (int i = 0; i < 8; i++)
        #pragma unroll
        for (int j = 0; j < 8; j++) acc[i][j] = 0.0f;

    float4 a0 = *(const float4*)Ap0;
    float4 a1 = *(const float4*)Ap1;
    float4 b0 = *(const float4*)Bp0;
    float4 b1 = *(const float4*)Bp1;

    for (int k0 = 0; k0 < K; k0 += 16) {
        As[(lk + 0) * 132 + lr]      = a0.x;
        As[(lk + 1) * 132 + lr]      = a0.y;
        As[(lk + 2) * 132 + lr]      = a0.z;
        As[(lk + 3) * 132 + lr]      = a0.w;
        As[(lk + 0) * 132 + lr + 64] = a1.x;
        As[(lk + 1) * 132 + lr + 64] = a1.y;
        As[(lk + 2) * 132 + lr + 64] = a1.z;
        As[(lk + 3) * 132 + lr + 64] = a1.w;
        Bs[(lk + 0) * 132 + lr]      = b0.x;
        Bs[(lk + 1) * 132 + lr]      = b0.y;
        Bs[(lk + 2) * 132 + lr]      = b0.z;
        Bs[(lk + 3) * 132 + lr]      = b0.w;
        Bs[(lk + 0) * 132 + lr + 64] = b1.x;
        Bs[(lk + 1) * 132 + lr + 64] = b1.y;
        Bs[(lk + 2) * 132 + lr + 64] = b1.z;
        Bs[(lk + 3) * 132 + lr + 64] = b1.w;
        __syncthreads();

        if (k0 + 16 < K) {   // prefetch next slab (latency hidden under compute)
            a0 = *(const float4*)(Ap0 + k0 + 16);
            a1 = *(const float4*)(Ap1 + k0 + 16);
            b0 = *(const float4*)(Bp0 + k0 + 16);
            b1 = *(const float4*)(Bp1 + k0 + 16);
        }

        #pragma unroll
        for (int kk = 0; kk < 16; kk++) {
            float a[8], b[8];
            *(float4*)(a)     = *(const float4*)&As[kk * 132 + ty * 8];
            *(float4*)(a + 4) = *(const float4*)&As[kk * 132 + ty * 8 + 4];
            *(float4*)(b)     = *(const float4*)&Bs[kk * 132 + tx * 8];
            *(float4*)(b + 4) = *(const float4*)&Bs[kk * 132 + tx * 8 + 4];
            #pragma unroll
            for (int i = 0; i < 8; i++)
                #pragma unroll
                for (int j = 0; j < 8; j++)
                    acc[i][j] = fmaf(a[i], b[j], acc[i][j]);
        }
        __syncthreads();
    }

    #pragma unroll
    for (int i = 0; i < 8; i++) {
        float* Crow = C + (size_t)(bm + ty * 8 + i) * N + bn + tx * 8;
        float4 v0 = make_float4(acc[i][0], acc[i][1], acc[i][2], acc[i][3]);
        float4 v1 = make_float4(acc[i][4], acc[i][5], acc[i][6], acc[i][7]);
        *(float4*)Crow       = v0;
        *(float4*)(Crow + 4) = v1;
    }
}

// ---------------- per-head RMSNorm + RoPE (in place) ------------------------
// grid: (S, nh), block 128 (= HD). position = blockIdx.x (positions are arange).
__global__ __launch_bounds__(128) void rmsnorm_rope_kernel(float* __restrict__ x,
                                                           const float* __restrict__ w,
                                                           int nh)
{
    const int s = blockIdx.x, h = blockIdx.y, d = threadIdx.x;
    float* base = x + ((size_t)s * nh + h) * HD;

    float v  = base[d];
    float sq = v * v;
    #pragma unroll
    for (int off = 16; off; off >>= 1) sq += __shfl_xor_sync(0xffffffffu, sq, off);

    __shared__ float red[4];
    __shared__ float sv[HD];
    if ((d & 31) == 0) red[d >> 5] = sq;
    __syncthreads();
    float mean = (red[0] + red[1] + red[2] + red[3]) * (1.0f / 128.0f);
    float nv = w[d] * (v * rsqrtf(mean + 1e-6f));
    sv[d] = nv;
    __syncthreads();

    float other = (d < 64) ? -sv[d + 64] : sv[d - 64];
    float ang = (float)((double)s * g_invfreq[d & 63]);
    float c, sn;
    sincosf(ang, &sn, &c);
    base[d] = nv * c + other * sn;
}

// ---------------- causal flash attention ------------------------------------
// grid: (S/64, NH). 256 threads. Q tile 64 rows; stream K/V in 64-row tiles.
#define KST 132
#define PST 68
#define ATTN_SMEM ((3 * 64 * KST + 64 * PST) * (int)sizeof(float))

__global__ __launch_bounds__(256) void attn_kernel(const float* __restrict__ Qg,
                                                   const float* __restrict__ Kg,
                                                   const float* __restrict__ Vg,
                                                   float* __restrict__ Og)
{
    extern __shared__ float sm[];
    float* Qs = sm;                 // 64 x 132
    float* Ks = Qs + 64 * KST;      // 64 x 132
    float* Vs = Ks + 64 * KST;      // 64 x 132
    float* Ps = Vs + 64 * KST;      // 64 x 68

    const int qt  = blockIdx.x;
    const int h   = blockIdx.y;
    const int kvh = h >> 2;         // GQA: 4 q-heads per kv head
    const int t   = threadIdx.x;
    const int ty  = t >> 4;         // 0..15  (4 q rows each)
    const int tx  = t & 15;         // 0..15  (keys tx+16j / dims tx*8..)

    // load Q tile (64 x 128)
    #pragma unroll
    for (int u = 0; u < 8; u++) {
        int idx = t + u * 256;
        int row = idx >> 5;
        int dc  = (idx & 31) << 2;
        float4 qv = *(const float4*)&Qg[((size_t)(qt * 64 + row) * NH + h) * HD + dc];
        *(float4*)&Qs[row * KST + dc] = qv;
    }

    float m[4], l[4], o[4][8];
    #pragma unroll
    for (int i = 0; i < 4; i++) {
        m[i] = -1e30f; l[i] = 0.0f;
        #pragma unroll
        for (int d = 0; d < 8; d++) o[i][d] = 0.0f;
    }
    const float scale = 0.08838834764831845f;   // 1/sqrt(128)

    for (int kt = 0; kt <= qt; kt++) {
        __syncthreads();   // Q loaded (first iter) / prev PV done with Ks,Vs,Ps
        #pragma unroll
        for (int u = 0; u < 8; u++) {
            int idx = t + u * 256;
            int row = idx >> 5;
            int dc  = (idx & 31) << 2;
            size_t g = ((size_t)(kt * 64 + row) * NKV + kvh) * HD + dc;
            *(float4*)&Ks[row * KST + dc] = *(const float4*)&Kg[g];
            *(float4*)&Vs[row * KST + dc] = *(const float4*)&Vg[g];
        }
        __syncthreads();

        // S = Q K^T  (each thread: 4 rows x 4 keys)
        float acc[4][4];
        #pragma unroll
        for (int i = 0; i < 4; i++)
            #pragma unroll
            for (int j = 0; j < 4; j++) acc[i][j] = 0.0f;

        for (int d = 0; d < 128; d += 4) {
            float4 qf[4], kf[4];
            #pragma unroll
            for (int i = 0; i < 4; i++) qf[i] = *(const float4*)&Qs[(ty * 4 + i) * KST + d];
            #pragma unroll
            for (int j = 0; j < 4; j++) kf[j] = *(const float4*)&Ks[(tx + 16 * j) * KST + d];
            #pragma unroll
            for (int i = 0; i < 4; i++)
                #pragma unroll
                for (int j = 0; j < 4; j++)
                    acc[i][j] += qf[i].x * kf[j].x + qf[i].y * kf[j].y +
                                 qf[i].z * kf[j].z + qf[i].w * kf[j].w;
        }

        // scale + causal mask (only diagonal tile needs masking)
        #pragma unroll
        for (int i = 0; i < 4; i++)
            #pragma unroll
            for (int j = 0; j < 4; j++) {
                float v = acc[i][j] * scale;
                if (kt == qt && (tx + 16 * j) > (ty * 4 + i)) v = -1e30f;
                acc[i][j] = v;
            }

        // online softmax (row stats reduced over the 16-lane half-warp)
        #pragma unroll
        for (int i = 0; i < 4; i++) {
            float mt = fmaxf(fmaxf(acc[i][0], acc[i][1]), fmaxf(acc[i][2], acc[i][3]));
            #pragma unroll
            for (int off = 8; off; off >>= 1)
                mt = fmaxf(mt, __shfl_xor_sync(0xffffffffu, mt, off));
            float mn = fmaxf(m[i], mt);
            float p[4], ls = 0.0f;
            #pragma unroll
            for (int j = 0; j < 4; j++) { p[j] = __expf(acc[i][j] - mn); ls += p[j]; }
            #pragma unroll
            for (int off = 8; off; off >>= 1)
                ls += __shfl_xor_sync(0xffffffffu, ls, off);
            float alpha = __expf(m[i] - mn);
            m[i] = mn;
            l[i] = l[i] * alpha + ls;
            #pragma unroll
            for (int d = 0; d < 8; d++) o[i][d] *= alpha;
            #pragma unroll
            for (int j = 0; j < 4; j++) Ps[(ty * 4 + i) * PST + tx + 16 * j] = p[j];
        }
        __syncwarp();

        // O += P V (each thread: its 4 rows x 8 dims at tx*8)
        for (int k = 0; k < 64; k++) {
            float4 v0 = *(const float4*)&Vs[k * KST + tx * 8];
            float4 v1 = *(const float4*)&Vs[k * KST + tx * 8 + 4];
            #pragma unroll
            for (int i = 0; i < 4; i++) {
                float p = Ps[(ty * 4 + i) * PST + k];
                o[i][0] = fmaf(p, v0.x, o[i][0]);
                o[i][1] = fmaf(p, v0.y, o[i][1]);
                o[i][2] = fmaf(p, v0.z, o[i][2]);
                o[i][3] = fmaf(p, v0.w, o[i][3]);
                o[i][4] = fmaf(p, v1.x, o[i][4]);
                o[i][5] = fmaf(p, v1.y, o[i][5]);
                o[i][6] = fmaf(p, v1.z, o[i][6]);
                o[i][7] = fmaf(p, v1.w, o[i][7]);
            }
        }
    }

    #pragma unroll
    for (int i = 0; i < 4; i++) {
        float inv = 1.0f / l[i];
        int row = qt * 64 + ty * 4 + i;
        float* out = Og + ((size_t)row * NH + h) * HD + tx * 8;
        float4 v0 = make_float4(o[i][0] * inv, o[i][1] * inv, o[i][2] * inv, o[i][3] * inv);
        float4 v1 = make_float4(o[i][4] * inv, o[i][5] * inv, o[i][6] * inv, o[i][7] * inv);
        *(float4*)out       = v0;
        *(float4*)(out + 4) = v1;
    }
}

// ---------------- launch -----------------------------------------------------
extern "C" void kernel_launch(void* const* d_in, const int* in_sizes, int n_in,
                              void* d_out, int out_size)
{
    const float* x  = (const float*)d_in[0];
    // d_in[1] = attention_mask (exactly causal -> implemented analytically)
    // d_in[2] = position_ids   (exactly arange  -> implemented analytically)
    const float* Wq = (const float*)d_in[3];
    const float* Wk = (const float*)d_in[4];
    const float* Wv = (const float*)d_in[5];
    const float* Wo = (const float*)d_in[6];
    const float* qw = (const float*)d_in[7];
    const float* kw = (const float*)d_in[8];
    float* out = (float*)d_out;

    void* p;
    cudaGetSymbolAddress(&p, g_q);   float* gq = (float*)p;
    cudaGetSymbolAddress(&p, g_k);   float* gk = (float*)p;
    cudaGetSymbolAddress(&p, g_v);   float* gv = (float*)p;
    cudaGetSymbolAddress(&p, g_ctx); float* gc = (float*)p;

    cudaFuncSetAttribute(attn_kernel, cudaFuncAttributeMaxDynamicSharedMemorySize,
                         ATTN_SMEM);

    init_invfreq_kernel<<<1, 64>>>();

    // projections
    sgemm_nt<<<dim3(HIDDEN / 128, SEQ / 128), 256>>>(x, Wq, gq, SEQ, NH * HD, HIDDEN);
    sgemm_nt<<<dim3((NKV * HD) / 128, SEQ / 128), 256>>>(x, Wk, gk, SEQ, NKV * HD, HIDDEN);
    sgemm_nt<<<dim3((NKV * HD) / 128, SEQ / 128), 256>>>(x, Wv, gv, SEQ, NKV * HD, HIDDEN);

    // q/k norm + rope (v untouched)
    rmsnorm_rope_kernel<<<dim3(SEQ, NH), 128>>>(gq, qw, NH);
    rmsnorm_rope_kernel<<<dim3(SEQ, NKV), 128>>>(gk, kw, NKV);

    // causal attention
    attn_kernel<<<dim3(SEQ / 64, NH), 256, ATTN_SMEM>>>(gq, gk, gv, gc);

    // output projection
    sgemm_nt<<<dim3(HIDDEN / 128, SEQ / 128), 256>>>(gc, Wo, out, SEQ, HIDDEN, HIDDEN);
}

// round 10
// speedup vs baseline: 3.1807x; 3.1807x over previous
#include <cuda_runtime.h>
#include <math.h>
#include <stdint.h>

#define SEQ 2048
#define HIDDEN 4096
#define NH 32
#define NKV 8
#define HD 128

// ---------------- scratch (device globals; no allocations allowed) ----------
__device__ float g_q[SEQ * NH * HD];     // [S, H, D]
__device__ float g_k[SEQ * NKV * HD];    // [S, KV, D]
__device__ float g_v[SEQ * NKV * HD];    // [S, KV, D]
__device__ float g_ctx[SEQ * NH * HD];   // [S, H, D]
__device__ double g_invfreq[64];

// ======================= PTX helpers (sm_80-era, portable) ==================
__device__ __forceinline__ uint32_t smem_u32(const void* p) {
    uint32_t a;
    asm("{ .reg .u64 t; cvta.to.shared.u64 t, %1; cvt.u32.u64 %0, t; }"
        : "=r"(a) : "l"(p));
    return a;
}

#define LDSM_X4(r0, r1, r2, r3, addr)                                         \
    asm volatile("ldmatrix.sync.aligned.m8n8.x4.shared.b16 {%0,%1,%2,%3}, [%4];" \
                 : "=r"(r0), "=r"(r1), "=r"(r2), "=r"(r3) : "r"(addr))

#define MMA_TF32(d, a0, a1, a2, a3, b0, b1)                                   \
    asm volatile("mma.sync.aligned.m16n8k8.row.col.f32.tf32.tf32.f32 "        \
                 "{%0,%1,%2,%3}, {%4,%5,%6,%7}, {%8,%9}, {%0,%1,%2,%3};"      \
                 : "+f"((d)[0]), "+f"((d)[1]), "+f"((d)[2]), "+f"((d)[3])     \
                 : "r"(a0), "r"(a1), "r"(a2), "r"(a3), "r"(b0), "r"(b1))

__device__ __forceinline__ float cvt_tf32(float x) {
    uint32_t u = __float_as_uint(x);
    asm("cvt.rna.tf32.f32 %0, %0;" : "+r"(u));
    return __uint_as_float(u);
}
__device__ __forceinline__ float4 cvt_tf32_f4(float4 v) {
    v.x = cvt_tf32(v.x); v.y = cvt_tf32(v.y);
    v.z = cvt_tf32(v.z); v.w = cvt_tf32(v.w);
    return v;
}

// 128B-row swizzle (16B granules): XOR bits[6:4] with row%8
#define SWZ(off)  ((off) ^ (((off) >> 3) & 0x70))
// 512B-row swizzle: XOR bits[6:4] with row%8 (row bits live at [11:9])
#define SWQ(off)  ((off) ^ ((((off) >> 9) & 7) << 4))

// ---------------- rope freq table (double precision) ------------------------
__global__ void init_invfreq_kernel() {
    int i = threadIdx.x;
    if (i < 64) g_invfreq[i] = exp(-((double)i) * (log(1.0e6) / 64.0));
}

// ================= tf32 mma GEMM: C[M,N] = A[M,K] @ B[N,K]^T ================
// CTA 128x128, K-slab 32, double buffered. 256 threads = 8 warps (2m x 4n),
// warp tile 64x32. Data is tf32-converted on the LDG->STS path.
#define GS_STAGE 32768
#define GSM_TOTAL 65536

__global__ __launch_bounds__(256) void gemm_mma(const float* __restrict__ A,
                                                const float* __restrict__ B,
                                                float* __restrict__ C,
                                                int M, int N, int K)
{
    extern __shared__ char sm[];
    const uint32_t smb = smem_u32(sm);
    const int t = threadIdx.x, lane = t & 31, wid = t >> 5;
    const int bm = blockIdx.y * 128, bn = blockIdx.x * 128;
    const int wm = (wid & 1) * 64, wn = (wid >> 1) * 32;

    // ldmatrix per-thread byte offsets inside a 128x32f tile (128B rows)
    const int lr8 = lane & 7;
    uint32_t a_row[4], b_row[2];
    #pragma unroll
    for (int mt = 0; mt < 4; mt++) {
        int r = wm + mt * 16 + lr8 + ((lane & 8) ? 8 : 0);
        a_row[mt] = (uint32_t)(r * 128 + ((lane & 16) ? 16 : 0));
    }
    #pragma unroll
    for (int hh = 0; hh < 2; hh++) {
        int r = wn + hh * 16 + lr8 + ((lane & 16) ? 8 : 0);
        b_row[hh] = (uint32_t)(r * 128 + ((lane & 8) ? 16 : 0));
    }

    const int grow = t >> 3;            // 0..31
    const int gcol = (t & 7) * 4;       // float col
    const uint32_t sts_off = SWZ((uint32_t)(grow * 128 + gcol * 4));
    const float* Ag = A + (size_t)(bm + grow) * K + gcol;
    const float* Bg = B + (size_t)(bn + grow) * K + gcol;

    float d[4][4][4];
    #pragma unroll
    for (int i = 0; i < 4; i++)
        #pragma unroll
        for (int j = 0; j < 4; j++)
            #pragma unroll
            for (int x = 0; x < 4; x++) d[i][j][x] = 0.0f;

    // preload slab 0
    #pragma unroll
    for (int u = 0; u < 4; u++) {
        float4 av = cvt_tf32_f4(*(const float4*)(Ag + (size_t)u * 32 * K));
        float4 bv = cvt_tf32_f4(*(const float4*)(Bg + (size_t)u * 32 * K));
        *(float4*)(sm + sts_off + u * 4096) = av;
        *(float4*)(sm + 16384 + sts_off + u * 4096) = bv;
    }
    __syncthreads();

    const int NK = K >> 5;
    float4 ra[4], rb[4];
    for (int kt = 0; kt < NK; kt++) {
        const int cur = kt & 1;
        if (kt + 1 < NK) {
            const float* An = Ag + (size_t)(kt + 1) * 32;
            const float* Bn = Bg + (size_t)(kt + 1) * 32;
            #pragma unroll
            for (int u = 0; u < 4; u++) {
                ra[u] = *(const float4*)(An + (size_t)u * 32 * K);
                rb[u] = *(const float4*)(Bn + (size_t)u * 32 * K);
            }
        }
        const uint32_t sA = smb + cur * GS_STAGE;
        const uint32_t sB = sA + 16384;
        #pragma unroll
        for (int ks = 0; ks < 4; ks++) {
            uint32_t a[4][4], b[2][4];
            #pragma unroll
            for (int mt = 0; mt < 4; mt++)
                LDSM_X4(a[mt][0], a[mt][1], a[mt][2], a[mt][3],
                        sA + SWZ(a_row[mt] + ks * 32));
            #pragma unroll
            for (int hh = 0; hh < 2; hh++)
                LDSM_X4(b[hh][0], b[hh][1], b[hh][2], b[hh][3],
                        sB + SWZ(b_row[hh] + ks * 32));
            #pragma unroll
            for (int mt = 0; mt < 4; mt++) {
                MMA_TF32(d[mt][0], a[mt][0], a[mt][1], a[mt][2], a[mt][3], b[0][0], b[0][1]);
                MMA_TF32(d[mt][1], a[mt][0], a[mt][1], a[mt][2], a[mt][3], b[0][2], b[0][3]);
                MMA_TF32(d[mt][2], a[mt][0], a[mt][1], a[mt][2], a[mt][3], b[1][0], b[1][1]);
                MMA_TF32(d[mt][3], a[mt][0], a[mt][1], a[mt][2], a[mt][3], b[1][2], b[1][3]);
            }
        }
        if (kt + 1 < NK) {
            char* dst = sm + (1 - cur) * GS_STAGE;
            #pragma unroll
            for (int u = 0; u < 4; u++) {
                *(float4*)(dst + sts_off + u * 4096) = cvt_tf32_f4(ra[u]);
                *(float4*)(dst + 16384 + sts_off + u * 4096) = cvt_tf32_f4(rb[u]);
            }
        }
        __syncthreads();
    }

    const int r0 = bm + wm + (lane >> 2);
    const int c0 = bn + wn + 2 * (lane & 3);
    #pragma unroll
    for (int mt = 0; mt < 4; mt++)
        #pragma unroll
        for (int nt = 0; nt < 4; nt++) {
            float* p0 = C + (size_t)(r0 + mt * 16) * N + c0 + nt * 8;
            *(float2*)p0 = make_float2(d[mt][nt][0], d[mt][nt][1]);
            float* p1 = p0 + (size_t)8 * N;
            *(float2*)p1 = make_float2(d[mt][nt][2], d[mt][nt][3]);
        }
}

// ---------------- per-head RMSNorm + RoPE (in place, + scale + tf32 round) --
__global__ __launch_bounds__(128) void rmsnorm_rope_kernel(float* __restrict__ x,
                                                           const float* __restrict__ w,
                                                           int nh, float scale)
{
    const int s = blockIdx.x, h = blockIdx.y, d = threadIdx.x;
    float* base = x + ((size_t)s * nh + h) * HD;

    float v  = base[d];
    float sq = v * v;
    #pragma unroll
    for (int off = 16; off; off >>= 1) sq += __shfl_xor_sync(0xffffffffu, sq, off);

    __shared__ float red[4];
    __shared__ float sv[HD];
    if ((d & 31) == 0) red[d >> 5] = sq;
    __syncthreads();
    float mean = (red[0] + red[1] + red[2] + red[3]) * (1.0f / 128.0f);
    float nv = w[d] * (v * rsqrtf(mean + 1e-6f));
    sv[d] = nv;
    __syncthreads();

    float other = (d < 64) ? -sv[d + 64] : sv[d - 64];
    float ang = (float)((double)s * g_invfreq[d & 63]);
    float c, sn;
    sincosf(ang, &sn, &c);
    base[d] = cvt_tf32((nv * c + other * sn) * scale);
}

// ================= causal flash attention on tf32 mma =======================
// Q tile 128 rows, K tile 64. 256 threads = 8 warps, warp = 16 q-rows.
#define VT_STRIDE 68    // floats (272B rows, 16B aligned, self-swizzling)
#define PS_STRIDE 68
#define ATT_QS 0
#define ATT_KS 65536
#define ATT_VT 98304                       // 128 x 68 x 4 = 34816
#define ATT_PS 133120                      // 128 x 68 x 4 = 34816
#define ATT_SMEM 167936

__global__ __launch_bounds__(256) void attn_mma(const float* __restrict__ Qg,
                                                const float* __restrict__ Kg,
                                                const float* __restrict__ Vg,
                                                float* __restrict__ Og)
{
    extern __shared__ char sm[];
    const uint32_t smb = smem_u32(sm);
    const int t = threadIdx.x, lane = t & 31, wid = t >> 5;
    const int qb = blockIdx.x, h = blockIdx.y, kvh = h >> 2;
    const int q0 = qb * 128;
    const int wbase = wid * 16;

    // Q tile -> Qs (already tf32 + pre-scaled by rope kernel)
    #pragma unroll
    for (int u = 0; u < 16; u++) {
        int idx = t + u * 256;
        int row = idx >> 5, col = (idx & 31) * 4;
        float4 v = *(const float4*)&Qg[((size_t)(q0 + row) * NH + h) * HD + col];
        *(float4*)(sm + ATT_QS + SWQ((uint32_t)(row * 512 + col * 4))) = v;
    }

    float o[16][4];
    #pragma unroll
    for (int i = 0; i < 16; i++)
        #pragma unroll
        for (int x = 0; x < 4; x++) o[i][x] = 0.0f;
    float m0 = -1e30f, m1 = -1e30f, l0 = 0.0f, l1 = 0.0f;

    const int lr8 = lane & 7;
    const uint32_t qa_row = (uint32_t)((wbase + lr8 + ((lane & 8) ? 8 : 0)) * 512
                                       + ((lane & 16) ? 16 : 0));
    uint32_t kb_row[4];
    #pragma unroll
    for (int hh = 0; hh < 4; hh++)
        kb_row[hh] = (uint32_t)((hh * 16 + lr8 + ((lane & 16) ? 8 : 0)) * 512
                                + ((lane & 8) ? 16 : 0));
    const uint32_t pa_row = (uint32_t)((wbase + lr8 + ((lane & 8) ? 8 : 0)) * (PS_STRIDE * 4)
                                       + ((lane & 16) ? 16 : 0));
    uint32_t vb_row[8];
    #pragma unroll
    for (int hh = 0; hh < 8; hh++)
        vb_row[hh] = (uint32_t)((hh * 16 + lr8 + ((lane & 16) ? 8 : 0)) * (VT_STRIDE * 4)
                                + ((lane & 8) ? 16 : 0));

    const int nkt = 2 * qb + 2;
    for (int kt = 0; kt < nkt; kt++) {
        __syncthreads();
        // K tile (tf32 already) -> Ks
        #pragma unroll
        for (int u = 0; u < 8; u++) {
            int idx = t + u * 256;
            int row = idx >> 5, col = (idx & 31) * 4;
            float4 v = *(const float4*)&Kg[((size_t)(kt * 64 + row) * NKV + kvh) * HD + col];
            *(float4*)(sm + ATT_KS + SWQ((uint32_t)(row * 512 + col * 4))) = v;
        }
        // V tile -> Vt (transposed to dim-major, tf32-converted)
        {
            int dd = t & 127, sh = (t >> 7) * 32;
            const float* vg = &Vg[((size_t)(kt * 64 + sh) * NKV + kvh) * HD + dd];
            float* vt = (float*)(sm + ATT_VT) + dd * VT_STRIDE + sh;
            #pragma unroll
            for (int s = 0; s < 32; s++)
                vt[s] = cvt_tf32(vg[(size_t)s * NKV * HD]);
        }
        __syncthreads();

        const bool skip = (kt == 2 * qb + 1) && (wid < 4);
        const bool needmask = (kt >= 2 * qb);

        if (!skip) {
            float s[8][4];
            #pragma unroll
            for (int i = 0; i < 8; i++)
                #pragma unroll
                for (int x = 0; x < 4; x++) s[i][x] = 0.0f;

            #pragma unroll
            for (int ks = 0; ks < 16; ks++) {
                uint32_t a[4], b[4][4];
                LDSM_X4(a[0], a[1], a[2], a[3],
                        smb + ATT_QS + SWQ(qa_row + ks * 32));
                #pragma unroll
                for (int hh = 0; hh < 4; hh++)
                    LDSM_X4(b[hh][0], b[hh][1], b[hh][2], b[hh][3],
                            smb + ATT_KS + SWQ(kb_row[hh] + ks * 32));
                #pragma unroll
                for (int nt = 0; nt < 8; nt++)
                    MMA_TF32(s[nt], a[0], a[1], a[2], a[3],
                             b[nt >> 1][(nt & 1) * 2], b[nt >> 1][(nt & 1) * 2 + 1]);
            }

            if (needmask) {
                const int r0 = q0 + wbase + (lane >> 2);
                #pragma unroll
                for (int nt = 0; nt < 8; nt++) {
                    int cbase = kt * 64 + nt * 8 + 2 * (lane & 3);
                    if (cbase > r0)     s[nt][0] = -1e30f;
                    if (cbase + 1 > r0) s[nt][1] = -1e30f;
                    if (cbase > r0 + 8)     s[nt][2] = -1e30f;
                    if (cbase + 1 > r0 + 8) s[nt][3] = -1e30f;
                }
            }

            // online softmax (rows r and r+8; 4-lane groups share a row)
            float mx0 = -1e30f, mx1 = -1e30f;
            #pragma unroll
            for (int nt = 0; nt < 8; nt++) {
                mx0 = fmaxf(mx0, fmaxf(s[nt][0], s[nt][1]));
                mx1 = fmaxf(mx1, fmaxf(s[nt][2], s[nt][3]));
            }
            mx0 = fmaxf(mx0, __shfl_xor_sync(0xffffffffu, mx0, 1));
            mx0 = fmaxf(mx0, __shfl_xor_sync(0xffffffffu, mx0, 2));
            mx1 = fmaxf(mx1, __shfl_xor_sync(0xffffffffu, mx1, 1));
            mx1 = fmaxf(mx1, __shfl_xor_sync(0xffffffffu, mx1, 2));
            float mn0 = fmaxf(m0, mx0), mn1 = fmaxf(m1, mx1);
            float al0 = __expf(m0 - mn0), al1 = __expf(m1 - mn1);
            m0 = mn0; m1 = mn1;
            float ls0 = 0.0f, ls1 = 0.0f;
            #pragma unroll
            for (int nt = 0; nt < 8; nt++) {
                s[nt][0] = __expf(s[nt][0] - mn0);
                s[nt][1] = __expf(s[nt][1] - mn0);
                s[nt][2] = __expf(s[nt][2] - mn1);
                s[nt][3] = __expf(s[nt][3] - mn1);
                ls0 += s[nt][0] + s[nt][1];
                ls1 += s[nt][2] + s[nt][3];
            }
            ls0 += __shfl_xor_sync(0xffffffffu, ls0, 1);
            ls0 += __shfl_xor_sync(0xffffffffu, ls0, 2);
            ls1 += __shfl_xor_sync(0xffffffffu, ls1, 1);
            ls1 += __shfl_xor_sync(0xffffffffu, ls1, 2);
            l0 = l0 * al0 + ls0;
            l1 = l1 * al1 + ls1;
            #pragma unroll
            for (int i = 0; i < 16; i++) {
                o[i][0] *= al0; o[i][1] *= al0;
                o[i][2] *= al1; o[i][3] *= al1;
            }
            // P -> Ps (tf32)
            {
                float* ps = (float*)(sm + ATT_PS);
                int prow = wbase + (lane >> 2);
                int pcol = 2 * (lane & 3);
                #pragma unroll
                for (int nt = 0; nt < 8; nt++) {
                    *(float2*)&ps[(size_t)prow * PS_STRIDE + nt * 8 + pcol] =
                        make_float2(cvt_tf32(s[nt][0]), cvt_tf32(s[nt][1]));
                    *(float2*)&ps[(size_t)(prow + 8) * PS_STRIDE + nt * 8 + pcol] =
                        make_float2(cvt_tf32(s[nt][2]), cvt_tf32(s[nt][3]));
                }
            }
        }
        __syncwarp();
        if (!skip) {
            #pragma unroll
            for (int ks = 0; ks < 8; ks++) {
                uint32_t a[4];
                LDSM_X4(a[0], a[1], a[2], a[3], smb + ATT_PS + pa_row + ks * 32);
                #pragma unroll
                for (int hh = 0; hh < 8; hh++) {
                    uint32_t b[4];
                    LDSM_X4(b[0], b[1], b[2], b[3],
                            smb + ATT_VT + vb_row[hh] + ks * 32);
                    MMA_TF32(o[2 * hh],     a[0], a[1], a[2], a[3], b[0], b[1]);
                    MMA_TF32(o[2 * hh + 1], a[0], a[1], a[2], a[3], b[2], b[3]);
                }
            }
        }
    }

    const float i0 = 1.0f / l0, i1 = 1.0f / l1;
    const int row = q0 + wbase + (lane >> 2);
    const int colb = 2 * (lane & 3);
    #pragma unroll
    for (int nt = 0; nt < 16; nt++) {
        float* p0 = Og + ((size_t)row * NH + h) * HD + nt * 8 + colb;
        *(float2*)p0 = make_float2(o[nt][0] * i0, o[nt][1] * i0);
        float* p1 = Og + ((size_t)(row + 8) * NH + h) * HD + nt * 8 + colb;
        *(float2*)p1 = make_float2(o[nt][2] * i1, o[nt][3] * i1);
    }
}

// ---------------- launch -----------------------------------------------------
extern "C" void kernel_launch(void* const* d_in, const int* in_sizes, int n_in,
                              void* d_out, int out_size)
{
    const float* x  = (const float*)d_in[0];
    const float* Wq = (const float*)d_in[3];
    const float* Wk = (const float*)d_in[4];
    const float* Wv = (const float*)d_in[5];
    const float* Wo = (const float*)d_in[6];
    const float* qw = (const float*)d_in[7];
    const float* kw = (const float*)d_in[8];
    float* out = (float*)d_out;

    void* p;
    cudaGetSymbolAddress(&p, g_q);   float* gq = (float*)p;
    cudaGetSymbolAddress(&p, g_k);   float* gk = (float*)p;
    cudaGetSymbolAddress(&p, g_v);   float* gv = (float*)p;
    cudaGetSymbolAddress(&p, g_ctx); float* gc = (float*)p;

    cudaFuncSetAttribute(gemm_mma, cudaFuncAttributeMaxDynamicSharedMemorySize, GSM_TOTAL);
    cudaFuncSetAttribute(attn_mma, cudaFuncAttributeMaxDynamicSharedMemorySize, ATT_SMEM);

    init_invfreq_kernel<<<1, 64>>>();

    gemm_mma<<<dim3(HIDDEN / 128, SEQ / 128), 256, GSM_TOTAL>>>(x, Wq, gq, SEQ, NH * HD, HIDDEN);
    gemm_mma<<<dim3((NKV * HD) / 128, SEQ / 128), 256, GSM_TOTAL>>>(x, Wk, gk, SEQ, NKV * HD, HIDDEN);
    gemm_mma<<<dim3((NKV * HD) / 128, SEQ / 128), 256, GSM_TOTAL>>>(x, Wv, gv, SEQ, NKV * HD, HIDDEN);

    // q: fold in 1/sqrt(D); k: scale 1. Both rounded to tf32 for the mma attn.
    rmsnorm_rope_kernel<<<dim3(SEQ, NH), 128>>>(gq, qw, NH, 0.08838834764831845f);
    rmsnorm_rope_kernel<<<dim3(SEQ, NKV), 128>>>(gk, kw, NKV, 1.0f);

    attn_mma<<<dim3(SEQ / 128, NH), 256, ATT_SMEM>>>(gq, gk, gv, gc);

    gemm_mma<<<dim3(HIDDEN / 128, SEQ / 128), 256, GSM_TOTAL>>>(gc, Wo, out, SEQ, HIDDEN, HIDDEN);
}

// round 12
// speedup vs baseline: 3.2477x; 1.0211x over previous
#include <cuda_runtime.h>
#include <math.h>
#include <stdint.h>

#define SEQ 2048
#define HIDDEN 4096
#define NH 32
#define NKV 8
#define HD 128

// ---------------- scratch (device globals; no allocations allowed) ----------
__device__ float g_q[SEQ * NH * HD];      // [S, H, D]
__device__ float g_k[SEQ * NKV * HD];     // [S, KV, D]
__device__ float g_v[SEQ * NKV * HD];     // [S, KV, D]
__device__ float g_vt[NKV * HD * SEQ];    // [KV, D, S]  (tf32, pi-permuted in s%8)
__device__ float g_ctx[SEQ * NH * HD];    // [S, H, D]
__device__ double g_invfreq[64];

// ======================= PTX helpers (sm_80-era, portable) ==================
__device__ __forceinline__ uint32_t smem_u32(const void* p) {
    uint32_t a;
    asm("{ .reg .u64 t; cvta.to.shared.u64 t, %1; cvt.u32.u64 %0, t; }"
        : "=r"(a) : "l"(p));
    return a;
}

#define LDSM_X4(r0, r1, r2, r3, addr)                                         \
    asm volatile("ldmatrix.sync.aligned.m8n8.x4.shared.b16 {%0,%1,%2,%3}, [%4];" \
                 : "=r"(r0), "=r"(r1), "=r"(r2), "=r"(r3) : "r"(addr))

#define MMA_TF32(d, a0, a1, a2, a3, b0, b1)                                   \
    asm volatile("mma.sync.aligned.m16n8k8.row.col.f32.tf32.tf32.f32 "        \
                 "{%0,%1,%2,%3}, {%4,%5,%6,%7}, {%8,%9}, {%0,%1,%2,%3};"      \
                 : "+f"((d)[0]), "+f"((d)[1]), "+f"((d)[2]), "+f"((d)[3])     \
                 : "r"(a0), "r"(a1), "r"(a2), "r"(a3), "r"(b0), "r"(b1))

#define CP_ASYNC16(dst, src)                                                  \
    asm volatile("cp.async.cg.shared.global [%0], [%1], 16;"                  \
                 :: "r"(dst), "l"(src) : "memory")
#define CP_COMMIT() asm volatile("cp.async.commit_group;" ::: "memory")
#define CP_WAIT1()  asm volatile("cp.async.wait_group 1;" ::: "memory")
#define CP_WAIT0()  asm volatile("cp.async.wait_group 0;" ::: "memory")

__device__ __forceinline__ float cvt_tf32(float x) {
    uint32_t u = __float_as_uint(x);
    asm("cvt.rna.tf32.f32 %0, %0;" : "+r"(u));
    return __uint_as_float(u);
}
__device__ __forceinline__ uint32_t cvt_tf32_bits(float x) {
    uint32_t u = __float_as_uint(x);
    asm("cvt.rna.tf32.f32 %0, %0;" : "+r"(u));
    return u;
}
__device__ __forceinline__ float4 cvt_tf32_f4(float4 v) {
    v.x = cvt_tf32(v.x); v.y = cvt_tf32(v.y);
    v.z = cvt_tf32(v.z); v.w = cvt_tf32(v.w);
    return v;
}

// 128B-row swizzle (16B granules): XOR bits[6:4] with row%8
#define SWZ(off)  ((off) ^ (((off) >> 3) & 0x70))
// 512B-row swizzle: XOR bits[6:4] with row%8 (row bits live at [11:9])
#define SWQ(off)  ((off) ^ ((((off) >> 9) & 7) << 4))

// ---------------- rope freq table (double precision) ------------------------
__global__ void init_invfreq_kernel() {
    int i = threadIdx.x;
    if (i < 64) g_invfreq[i] = exp(-((double)i) * (log(1.0e6) / 64.0));
}

// ================= tf32 mma GEMM: C[M,N] = A[M,K] @ B[N,K]^T ================
#define GS_STAGE 32768
#define GSM_TOTAL 65536

__global__ __launch_bounds__(256) void gemm_mma(const float* __restrict__ A,
                                                const float* __restrict__ B,
                                                float* __restrict__ C,
                                                int M, int N, int K)
{
    extern __shared__ char sm[];
    const uint32_t smb = smem_u32(sm);
    const int t = threadIdx.x, lane = t & 31, wid = t >> 5;
    const int bm = blockIdx.y * 128, bn = blockIdx.x * 128;
    const int wm = (wid & 1) * 64, wn = (wid >> 1) * 32;

    const int lr8 = lane & 7;
    uint32_t a_row[4], b_row[2];
    #pragma unroll
    for (int mt = 0; mt < 4; mt++) {
        int r = wm + mt * 16 + lr8 + ((lane & 8) ? 8 : 0);
        a_row[mt] = (uint32_t)(r * 128 + ((lane & 16) ? 16 : 0));
    }
    #pragma unroll
    for (int hh = 0; hh < 2; hh++) {
        int r = wn + hh * 16 + lr8 + ((lane & 16) ? 8 : 0);
        b_row[hh] = (uint32_t)(r * 128 + ((lane & 8) ? 16 : 0));
    }

    const int grow = t >> 3;
    const int gcol = (t & 7) * 4;
    const uint32_t sts_off = SWZ((uint32_t)(grow * 128 + gcol * 4));
    const float* Ag = A + (size_t)(bm + grow) * K + gcol;
    const float* Bg = B + (size_t)(bn + grow) * K + gcol;

    float d[4][4][4];
    #pragma unroll
    for (int i = 0; i < 4; i++)
        #pragma unroll
        for (int j = 0; j < 4; j++)
            #pragma unroll
            for (int x = 0; x < 4; x++) d[i][j][x] = 0.0f;

    #pragma unroll
    for (int u = 0; u < 4; u++) {
        float4 av = cvt_tf32_f4(*(const float4*)(Ag + (size_t)u * 32 * K));
        float4 bv = cvt_tf32_f4(*(const float4*)(Bg + (size_t)u * 32 * K));
        *(float4*)(sm + sts_off + u * 4096) = av;
        *(float4*)(sm + 16384 + sts_off + u * 4096) = bv;
    }
    __syncthreads();

    const int NK = K >> 5;
    float4 ra[4], rb[4];
    for (int kt = 0; kt < NK; kt++) {
        const int cur = kt & 1;
        if (kt + 1 < NK) {
            const float* An = Ag + (size_t)(kt + 1) * 32;
            const float* Bn = Bg + (size_t)(kt + 1) * 32;
            #pragma unroll
            for (int u = 0; u < 4; u++) {
                ra[u] = *(const float4*)(An + (size_t)u * 32 * K);
                rb[u] = *(const float4*)(Bn + (size_t)u * 32 * K);
            }
        }
        const uint32_t sA = smb + cur * GS_STAGE;
        const uint32_t sB = sA + 16384;
        #pragma unroll
        for (int ks = 0; ks < 4; ks++) {
            uint32_t a[4][4], b[2][4];
            #pragma unroll
            for (int mt = 0; mt < 4; mt++)
                LDSM_X4(a[mt][0], a[mt][1], a[mt][2], a[mt][3],
                        sA + SWZ(a_row[mt] + ks * 32));
            #pragma unroll
            for (int hh = 0; hh < 2; hh++)
                LDSM_X4(b[hh][0], b[hh][1], b[hh][2], b[hh][3],
                        sB + SWZ(b_row[hh] + ks * 32));
            #pragma unroll
            for (int mt = 0; mt < 4; mt++) {
                MMA_TF32(d[mt][0], a[mt][0], a[mt][1], a[mt][2], a[mt][3], b[0][0], b[0][1]);
                MMA_TF32(d[mt][1], a[mt][0], a[mt][1], a[mt][2], a[mt][3], b[0][2], b[0][3]);
                MMA_TF32(d[mt][2], a[mt][0], a[mt][1], a[mt][2], a[mt][3], b[1][0], b[1][1]);
                MMA_TF32(d[mt][3], a[mt][0], a[mt][1], a[mt][2], a[mt][3], b[1][2], b[1][3]);
            }
        }
        if (kt + 1 < NK) {
            char* dst = sm + (1 - cur) * GS_STAGE;
            #pragma unroll
            for (int u = 0; u < 4; u++) {
                *(float4*)(dst + sts_off + u * 4096) = cvt_tf32_f4(ra[u]);
                *(float4*)(dst + 16384 + sts_off + u * 4096) = cvt_tf32_f4(rb[u]);
            }
        }
        __syncthreads();
    }

    const int r0 = bm + wm + (lane >> 2);
    const int c0 = bn + wn + 2 * (lane & 3);
    #pragma unroll
    for (int mt = 0; mt < 4; mt++)
        #pragma unroll
        for (int nt = 0; nt < 4; nt++) {
            float* p0 = C + (size_t)(r0 + mt * 16) * N + c0 + nt * 8;
            *(float2*)p0 = make_float2(d[mt][nt][0], d[mt][nt][1]);
            float* p1 = p0 + (size_t)8 * N;
            *(float2*)p1 = make_float2(d[mt][nt][2], d[mt][nt][3]);
        }
}

// ---------------- per-head RMSNorm + RoPE (in place, + scale + tf32 round) --
__global__ __launch_bounds__(128) void rmsnorm_rope_kernel(float* __restrict__ x,
                                                           const float* __restrict__ w,
                                                           int nh, float scale)
{
    const int s = blockIdx.x, h = blockIdx.y, d = threadIdx.x;
    float* base = x + ((size_t)s * nh + h) * HD;

    float v  = base[d];
    float sq = v * v;
    #pragma unroll
    for (int off = 16; off; off >>= 1) sq += __shfl_xor_sync(0xffffffffu, sq, off);

    __shared__ float red[4];
    __shared__ float sv[HD];
    if ((d & 31) == 0) red[d >> 5] = sq;
    __syncthreads();
    float mean = (red[0] + red[1] + red[2] + red[3]) * (1.0f / 128.0f);
    float nv = w[d] * (v * rsqrtf(mean + 1e-6f));
    sv[d] = nv;
    __syncthreads();

    float other = (d < 64) ? -sv[d + 64] : sv[d - 64];
    float ang = (float)((double)s * g_invfreq[d & 63]);
    float c, sn;
    sincosf(ang, &sn, &c);
    base[d] = cvt_tf32((nv * c + other * sn) * scale);
}

// ---------------- V pre-transpose: g_v[S,KV,D] -> g_vt[KV,D,S] (tf32) -------
// pi permutation baked into s%8 so softmax regs can be used directly as
// mma A-fragments: phys p holds logical j = (p<4) ? 2p : 2p-7.
__global__ __launch_bounds__(256) void transpose_v(const float* __restrict__ V,
                                                   float* __restrict__ Vt)
{
    __shared__ float tl[128][65];
    const int s0 = blockIdx.x * 64, kv = blockIdx.y, t = threadIdx.x;
    #pragma unroll
    for (int w = 0; w < 32; w++) {
        int idx = t + w * 256;
        int sl = idx >> 7, d = idx & 127;
        tl[d][sl] = cvt_tf32(V[((size_t)(s0 + sl) * NKV + kv) * HD + d]);
    }
    __syncthreads();
    #pragma unroll
    for (int w = 0; w < 32; w++) {
        int idx = t + w * 256;
        int d = idx >> 6, sp = idx & 63;
        int g = sp & 56;      // 8*(sp/8)
        int p = sp & 7;
        int slog = g + ((p < 4) ? 2 * p : 2 * p - 7);
        Vt[((size_t)kv * HD + d) * SEQ + s0 + sp] = tl[d][slog];
    }
}

// ================= causal flash attention on tf32 mma =======================
// Q tile 128 rows, K tile 64. cp.async double-buffered K + Vt stages.
// smem: Qs 64KB | stage0 {K 32KB, Vt 34KB} | stage1 {K, Vt}   = 196KB
#define ATT_KST   65536
#define ATT_STAGE 67584
#define ATT_SMEM  200704

__global__ __launch_bounds__(256) void attn_mma(const float* __restrict__ Qg,
                                                const float* __restrict__ Kg,
                                                const float* __restrict__ Vtg,
                                                float* __restrict__ Og)
{
    extern __shared__ char sm[];
    const uint32_t smb = smem_u32(sm);
    const int t = threadIdx.x, lane = t & 31, wid = t >> 5;
    const int qb = (int)gridDim.x - 1 - (int)blockIdx.x;   // LPT: heavy first
    const int h = blockIdx.y, kvh = h >> 2;
    const int q0 = qb * 128;
    const int wbase = wid * 16;

    // Q tile -> Qs (already tf32 + pre-scaled by rope kernel)
    #pragma unroll
    for (int u = 0; u < 16; u++) {
        int idx = t + u * 256;
        int row = idx >> 5, col = (idx & 31) * 4;
        float4 v = *(const float4*)&Qg[((size_t)(q0 + row) * NH + h) * HD + col];
        *(float4*)(sm + SWQ((uint32_t)(row * 512 + col * 4))) = v;
    }

    float o[16][4];
    #pragma unroll
    for (int i = 0; i < 16; i++)
        #pragma unroll
        for (int x = 0; x < 4; x++) o[i][x] = 0.0f;
    float m0 = -1e30f, m1 = -1e30f, l0 = 0.0f, l1 = 0.0f;

    const int lr8 = lane & 7;
    const uint32_t qa_row = (uint32_t)((wbase + lr8 + ((lane & 8) ? 8 : 0)) * 512
                                       + ((lane & 16) ? 16 : 0));
    uint32_t kb_row[4];
    #pragma unroll
    for (int hh = 0; hh < 4; hh++)
        kb_row[hh] = (uint32_t)((hh * 16 + lr8 + ((lane & 16) ? 8 : 0)) * 512
                                + ((lane & 8) ? 16 : 0));
    uint32_t vb_row[8];
    #pragma unroll
    for (int hh = 0; hh < 8; hh++)
        vb_row[hh] = (uint32_t)((hh * 16 + lr8 + ((lane & 16) ? 8 : 0)) * 272
                                + ((lane & 8) ? 16 : 0));

    const int nkt = 2 * qb + 2;
    const float* kbase_g = Kg + (size_t)kvh * HD;
    const float* vbase_g = Vtg + (size_t)kvh * HD * SEQ;

    auto issue_tile = [&](int kt2, int stg) {
        const uint32_t kb = smb + ATT_KST + (uint32_t)stg * ATT_STAGE;
        const uint32_t vb = kb + 32768;
        #pragma unroll
        for (int u = 0; u < 8; u++) {
            int idx = t + u * 256;
            int r = idx >> 5, c = idx & 31;
            uint32_t dst = kb + SWQ((uint32_t)(r * 512 + c * 16));
            const void* src = (const char*)(kbase_g + (size_t)(kt2 * 64 + r) * NKV * HD) + c * 16;
            CP_ASYNC16(dst, src);
        }
        #pragma unroll
        for (int u = 0; u < 8; u++) {
            int idx = t + u * 256;
            int dd = idx >> 4, c = idx & 15;
            uint32_t dst = vb + (uint32_t)(dd * 272 + c * 16);
            const void* src = (const char*)(vbase_g + (size_t)dd * SEQ + kt2 * 64) + c * 16;
            CP_ASYNC16(dst, src);
        }
    };

    issue_tile(0, 0);
    CP_COMMIT();

    for (int kt = 0; kt < nkt; kt++) {
        if (kt + 1 < nkt) {
            issue_tile(kt + 1, (kt + 1) & 1);
            CP_COMMIT();
            CP_WAIT1();
        } else {
            CP_WAIT0();
        }
        __syncthreads();

        const uint32_t sK = smb + ATT_KST + (uint32_t)(kt & 1) * ATT_STAGE;
        const uint32_t sV = sK + 32768;

        const bool skip = (kt == 2 * qb + 1) && (wid < 4);
        const bool needmask = (kt >= 2 * qb);

        if (!skip) {
            float s[8][4];
            #pragma unroll
            for (int i = 0; i < 8; i++)
                #pragma unroll
                for (int x = 0; x < 4; x++) s[i][x] = 0.0f;

            #pragma unroll
            for (int ks = 0; ks < 16; ks++) {
                uint32_t a[4], b[4][4];
                LDSM_X4(a[0], a[1], a[2], a[3], smb + SWQ(qa_row + ks * 32));
                #pragma unroll
                for (int hh = 0; hh < 4; hh++)
                    LDSM_X4(b[hh][0], b[hh][1], b[hh][2], b[hh][3],
                            sK + SWQ(kb_row[hh] + ks * 32));
                #pragma unroll
                for (int nt = 0; nt < 8; nt++)
                    MMA_TF32(s[nt], a[0], a[1], a[2], a[3],
                             b[nt >> 1][(nt & 1) * 2], b[nt >> 1][(nt & 1) * 2 + 1]);
            }

            if (needmask) {
                const int r0 = q0 + wbase + (lane >> 2);
                #pragma unroll
                for (int nt = 0; nt < 8; nt++) {
                    int cbase = kt * 64 + nt * 8 + 2 * (lane & 3);
                    if (cbase > r0)         s[nt][0] = -1e30f;
                    if (cbase + 1 > r0)     s[nt][1] = -1e30f;
                    if (cbase > r0 + 8)     s[nt][2] = -1e30f;
                    if (cbase + 1 > r0 + 8) s[nt][3] = -1e30f;
                }
            }

            // online softmax (rows r and r+8)
            float mx0 = -1e30f, mx1 = -1e30f;
            #pragma unroll
            for (int nt = 0; nt < 8; nt++) {
                mx0 = fmaxf(mx0, fmaxf(s[nt][0], s[nt][1]));
                mx1 = fmaxf(mx1, fmaxf(s[nt][2], s[nt][3]));
            }
            mx0 = fmaxf(mx0, __shfl_xor_sync(0xffffffffu, mx0, 1));
            mx0 = fmaxf(mx0, __shfl_xor_sync(0xffffffffu, mx0, 2));
            mx1 = fmaxf(mx1, __shfl_xor_sync(0xffffffffu, mx1, 1));
            mx1 = fmaxf(mx1, __shfl_xor_sync(0xffffffffu, mx1, 2));
            float mn0 = fmaxf(m0, mx0), mn1 = fmaxf(m1, mx1);
            float al0 = __expf(m0 - mn0), al1 = __expf(m1 - mn1);
            m0 = mn0; m1 = mn1;
            float ls0 = 0.0f, ls1 = 0.0f;
            #pragma unroll
            for (int nt = 0; nt < 8; nt++) {
                s[nt][0] = __expf(s[nt][0] - mn0);
                s[nt][1] = __expf(s[nt][1] - mn0);
                s[nt][2] = __expf(s[nt][2] - mn1);
                s[nt][3] = __expf(s[nt][3] - mn1);
                ls0 += s[nt][0] + s[nt][1];
                ls1 += s[nt][2] + s[nt][3];
            }
            ls0 += __shfl_xor_sync(0xffffffffu, ls0, 1);
            ls0 += __shfl_xor_sync(0xffffffffu, ls0, 2);
            ls1 += __shfl_xor_sync(0xffffffffu, ls1, 1);
            ls1 += __shfl_xor_sync(0xffffffffu, ls1, 2);
            l0 = l0 * al0 + ls0;
            l1 = l1 * al1 + ls1;
            #pragma unroll
            for (int i = 0; i < 16; i++) {
                o[i][0] *= al0; o[i][1] *= al0;
                o[i][2] *= al1; o[i][3] *= al1;
            }

            // PV: softmax regs used DIRECTLY as A-fragments.
            // hw a-frag = (a0:[r][c], a1:[r+8][c], a2:[r][c+4], a3:[r+8][c+4]);
            // with pi-permuted Vt rows these are s[ks][0], s[ks][2], s[ks][1], s[ks][3].
            #pragma unroll
            for (int ks = 0; ks < 8; ks++) {
                uint32_t pa0 = cvt_tf32_bits(s[ks][0]);
                uint32_t pa1 = cvt_tf32_bits(s[ks][2]);
                uint32_t pa2 = cvt_tf32_bits(s[ks][1]);
                uint32_t pa3 = cvt_tf32_bits(s[ks][3]);
                #pragma unroll
                for (int hh = 0; hh < 8; hh++) {
                    uint32_t b[4];
                    LDSM_X4(b[0], b[1], b[2], b[3], sV + vb_row[hh] + ks * 32);
                    MMA_TF32(o[2 * hh],     pa0, pa1, pa2, pa3, b[0], b[1]);
                    MMA_TF32(o[2 * hh + 1], pa0, pa1, pa2, pa3, b[2], b[3]);
                }
            }
        }
        __syncthreads();   // all warps done with stage buffers before overwrite
    }

    const float i0 = 1.0f / l0, i1 = 1.0f / l1;
    const int row = q0 + wbase + (lane >> 2);
    const int colb = 2 * (lane & 3);
    #pragma unroll
    for (int nt = 0; nt < 16; nt++) {
        float* p0 = Og + ((size_t)row * NH + h) * HD + nt * 8 + colb;
        *(float2*)p0 = make_float2(o[nt][0] * i0, o[nt][1] * i0);
        float* p1 = Og + ((size_t)(row + 8) * NH + h) * HD + nt * 8 + colb;
        *(float2*)p1 = make_float2(o[nt][2] * i1, o[nt][3] * i1);
    }
}

// ---------------- launch -----------------------------------------------------
extern "C" void kernel_launch(void* const* d_in, const int* in_sizes, int n_in,
                              void* d_out, int out_size)
{
    const float* x  = (const float*)d_in[0];
    const float* Wq = (const float*)d_in[3];
    const float* Wk = (const float*)d_in[4];
    const float* Wv = (const float*)d_in[5];
    const float* Wo = (const float*)d_in[6];
    const float* qw = (const float*)d_in[7];
    const float* kw = (const float*)d_in[8];
    float* out = (float*)d_out;

    void* p;
    cudaGetSymbolAddress(&p, g_q);   float* gq  = (float*)p;
    cudaGetSymbolAddress(&p, g_k);   float* gk  = (float*)p;
    cudaGetSymbolAddress(&p, g_v);   float* gv  = (float*)p;
    cudaGetSymbolAddress(&p, g_vt);  float* gvt = (float*)p;
    cudaGetSymbolAddress(&p, g_ctx); float* gc  = (float*)p;

    cudaFuncSetAttribute(gemm_mma, cudaFuncAttributeMaxDynamicSharedMemorySize, GSM_TOTAL);
    cudaFuncSetAttribute(attn_mma, cudaFuncAttributeMaxDynamicSharedMemorySize, ATT_SMEM);

    init_invfreq_kernel<<<1, 64>>>();

    gemm_mma<<<dim3(HIDDEN / 128, SEQ / 128), 256, GSM_TOTAL>>>(x, Wq, gq, SEQ, NH * HD, HIDDEN);
    gemm_mma<<<dim3((NKV * HD) / 128, SEQ / 128), 256, GSM_TOTAL>>>(x, Wk, gk, SEQ, NKV * HD, HIDDEN);
    gemm_mma<<<dim3((NKV * HD) / 128, SEQ / 128), 256, GSM_TOTAL>>>(x, Wv, gv, SEQ, NKV * HD, HIDDEN);

    transpose_v<<<dim3(SEQ / 64, NKV), 256>>>(gv, gvt);

    rmsnorm_rope_kernel<<<dim3(SEQ, NH), 128>>>(gq, qw, NH, 0.08838834764831845f);
    rmsnorm_rope_kernel<<<dim3(SEQ, NKV), 128>>>(gk, kw, NKV, 1.0f);

    attn_mma<<<dim3(SEQ / 128, NH), 256, ATT_SMEM>>>(gq, gk, gvt, gc);

    gemm_mma<<<dim3(HIDDEN / 128, SEQ / 128), 256, GSM_TOTAL>>>(gc, Wo, out, SEQ, HIDDEN, HIDDEN);
}

// round 14
// speedup vs baseline: 4.0114x; 1.2351x over previous
#include <cuda_runtime.h>
#include <math.h>
#include <stdint.h>

#define SEQ 2048
#define HIDDEN 4096
#define NH 32
#define NKV 8
#define HD 128

// ---------------- scratch (device globals; no allocations allowed) ----------
__device__ float g_q[SEQ * NH * HD];      // [S, H, D]
__device__ float g_k[SEQ * NKV * HD];     // [S, KV, D]
__device__ float g_v[SEQ * NKV * HD];     // [S, KV, D]
__device__ float g_vt[NKV * HD * SEQ];    // [KV, D, S]  (tf32, pi-permuted in s%8)
__device__ float g_ctx[SEQ * NH * HD];    // [S, H, D]  (tf32)
__device__ float g_xt[SEQ * HIDDEN];      // tf32 hidden states
__device__ float g_wq[NH * HD * HIDDEN];  // tf32 weights
__device__ float g_wk[NKV * HD * HIDDEN];
__device__ float g_wv[NKV * HD * HIDDEN];
__device__ float g_wo[HIDDEN * NH * HD];
__device__ double g_invfreq[64];

// ======================= PTX helpers (sm_80-era, portable) ==================
__device__ __forceinline__ uint32_t smem_u32(const void* p) {
    uint32_t a;
    asm("{ .reg .u64 t; cvta.to.shared.u64 t, %1; cvt.u32.u64 %0, t; }"
        : "=r"(a) : "l"(p));
    return a;
}

#define LDSM_X4(r0, r1, r2, r3, addr)                                         \
    asm volatile("ldmatrix.sync.aligned.m8n8.x4.shared.b16 {%0,%1,%2,%3}, [%4];" \
                 : "=r"(r0), "=r"(r1), "=r"(r2), "=r"(r3) : "r"(addr))

#define MMA_TF32(d, a0, a1, a2, a3, b0, b1)                                   \
    asm volatile("mma.sync.aligned.m16n8k8.row.col.f32.tf32.tf32.f32 "        \
                 "{%0,%1,%2,%3}, {%4,%5,%6,%7}, {%8,%9}, {%0,%1,%2,%3};"      \
                 : "+f"((d)[0]), "+f"((d)[1]), "+f"((d)[2]), "+f"((d)[3])     \
                 : "r"(a0), "r"(a1), "r"(a2), "r"(a3), "r"(b0), "r"(b1))

#define CP_ASYNC16(dst, src)                                                  \
    asm volatile("cp.async.cg.shared.global [%0], [%1], 16;"                  \
                 :: "r"(dst), "l"(src) : "memory")
#define CP_COMMIT() asm volatile("cp.async.commit_group;" ::: "memory")
#define CP_WAIT2()  asm volatile("cp.async.wait_group 2;" ::: "memory")
#define CP_WAIT1()  asm volatile("cp.async.wait_group 1;" ::: "memory")
#define CP_WAIT0()  asm volatile("cp.async.wait_group 0;" ::: "memory")

__device__ __forceinline__ float cvt_tf32(float x) {
    uint32_t u = __float_as_uint(x);
    asm("cvt.rna.tf32.f32 %0, %0;" : "+r"(u));
    return __uint_as_float(u);
}
__device__ __forceinline__ uint32_t cvt_tf32_bits(float x) {
    uint32_t u = __float_as_uint(x);
    asm("cvt.rna.tf32.f32 %0, %0;" : "+r"(u));
    return u;
}
__device__ __forceinline__ float4 cvt_tf32_f4(float4 v) {
    v.x = cvt_tf32(v.x); v.y = cvt_tf32(v.y);
    v.z = cvt_tf32(v.z); v.w = cvt_tf32(v.w);
    return v;
}

// 128B-row swizzle (16B granules): XOR bits[6:4] with row%8
#define SWZ(off)  ((off) ^ (((off) >> 3) & 0x70))
// 512B-row swizzle
#define SWQ(off)  ((off) ^ ((((off) >> 9) & 7) << 4))

// ---------------- init + elementwise tf32 convert ---------------------------
__global__ void init_invfreq_kernel() {
    int i = threadIdx.x;
    if (i < 64) g_invfreq[i] = exp(-((double)i) * (log(1.0e6) / 64.0));
}

__global__ __launch_bounds__(256) void cvt_tf32_kernel(const float* __restrict__ src,
                                                       float* __restrict__ dst, int n4)
{
    int i = blockIdx.x * 256 + threadIdx.x;
    if (i < n4) {
        float4 v = ((const float4*)src)[i];
        ((float4*)dst)[i] = cvt_tf32_f4(v);
    }
}

// ================= tf32 mma GEMM (inputs pre-converted to tf32) =============
// CTA 128x128, K-slab 32, 3-stage cp.async pipeline, 2 CTAs/SM.
#define GS_STAGE 32768
#define GSM_TOTAL 98304

__global__ __launch_bounds__(256, 2) void gemm_mma(const float* __restrict__ A,
                                                   const float* __restrict__ B,
                                                   float* __restrict__ C,
                                                   int M, int N, int K)
{
    extern __shared__ char sm[];
    const uint32_t smb = smem_u32(sm);
    const int t = threadIdx.x, lane = t & 31, wid = t >> 5;
    const int bm = blockIdx.y * 128, bn = blockIdx.x * 128;
    const int wm = (wid & 1) * 64, wn = (wid >> 1) * 32;

    const int lr8 = lane & 7;
    uint32_t a_row[4], b_row[2];
    #pragma unroll
    for (int mt = 0; mt < 4; mt++) {
        int r = wm + mt * 16 + lr8 + ((lane & 8) ? 8 : 0);
        a_row[mt] = (uint32_t)(r * 128 + ((lane & 16) ? 16 : 0));
    }
    #pragma unroll
    for (int hh = 0; hh < 2; hh++) {
        int r = wn + hh * 16 + lr8 + ((lane & 16) ? 8 : 0);
        b_row[hh] = (uint32_t)(r * 128 + ((lane & 8) ? 16 : 0));
    }

    // cp.async loader: thread covers rows (t>>3)+32u, 16B segment (t&7)
    const int crow = t >> 3;
    const int cseg = t & 7;
    const uint32_t adst = SWZ((uint32_t)(crow * 128 + cseg * 16));
    const float* Asrc = A + (size_t)(bm + crow) * K + cseg * 4;
    const float* Bsrc = B + (size_t)(bn + crow) * K + cseg * 4;

    float d[4][4][4];
    #pragma unroll
    for (int i = 0; i < 4; i++)
        #pragma unroll
        for (int j = 0; j < 4; j++)
            #pragma unroll
            for (int x = 0; x < 4; x++) d[i][j][x] = 0.0f;

    auto issue = [&](int kt2, int stg) {
        const uint32_t base = smb + (uint32_t)stg * GS_STAGE;
        #pragma unroll
        for (int u = 0; u < 4; u++) {
            CP_ASYNC16(base + adst + u * 4096,
                       Asrc + (size_t)u * 32 * K + kt2 * 32);
            CP_ASYNC16(base + 16384 + adst + u * 4096,
                       Bsrc + (size_t)u * 32 * K + kt2 * 32);
        }
    };

    issue(0, 0); CP_COMMIT();
    issue(1, 1); CP_COMMIT();

    const int NK = K >> 5;
    for (int kt = 0; kt < NK; kt++) {
        if (kt + 2 < NK) issue(kt + 2, (kt + 2) % 3);
        CP_COMMIT();
        CP_WAIT2();
        __syncthreads();                       // all threads' slab-kt data visible

        const uint32_t sA = smb + (uint32_t)(kt % 3) * GS_STAGE;
        const uint32_t sB = sA + 16384;
        #pragma unroll
        for (int ks = 0; ks < 4; ks++) {
            uint32_t a[4][4], b[2][4];
            #pragma unroll
            for (int mt = 0; mt < 4; mt++)
                LDSM_X4(a[mt][0], a[mt][1], a[mt][2], a[mt][3],
                        sA + SWZ(a_row[mt] + ks * 32));
            #pragma unroll
            for (int hh = 0; hh < 2; hh++)
                LDSM_X4(b[hh][0], b[hh][1], b[hh][2], b[hh][3],
                        sB + SWZ(b_row[hh] + ks * 32));
            #pragma unroll
            for (int mt = 0; mt < 4; mt++) {
                MMA_TF32(d[mt][0], a[mt][0], a[mt][1], a[mt][2], a[mt][3], b[0][0], b[0][1]);
                MMA_TF32(d[mt][1], a[mt][0], a[mt][1], a[mt][2], a[mt][3], b[0][2], b[0][3]);
                MMA_TF32(d[mt][2], a[mt][0], a[mt][1], a[mt][2], a[mt][3], b[1][0], b[1][1]);
                MMA_TF32(d[mt][3], a[mt][0], a[mt][1], a[mt][2], a[mt][3], b[1][2], b[1][3]);
            }
        }
        __syncthreads();                       // reuse protection for stage (kt)%3
    }

    const int r0 = bm + wm + (lane >> 2);
    const int c0 = bn + wn + 2 * (lane & 3);
    #pragma unroll
    for (int mt = 0; mt < 4; mt++)
        #pragma unroll
        for (int nt = 0; nt < 4; nt++) {
            float* p0 = C + (size_t)(r0 + mt * 16) * N + c0 + nt * 8;
            *(float2*)p0 = make_float2(d[mt][nt][0], d[mt][nt][1]);
            float* p1 = p0 + (size_t)8 * N;
            *(float2*)p1 = make_float2(d[mt][nt][2], d[mt][nt][3]);
        }
}

// ---------------- per-head RMSNorm + RoPE (in place, + scale + tf32 round) --
__global__ __launch_bounds__(128) void rmsnorm_rope_kernel(float* __restrict__ x,
                                                           const float* __restrict__ w,
                                                           int nh, float scale)
{
    const int s = blockIdx.x, h = blockIdx.y, d = threadIdx.x;
    float* base = x + ((size_t)s * nh + h) * HD;

    float v  = base[d];
    float sq = v * v;
    #pragma unroll
    for (int off = 16; off; off >>= 1) sq += __shfl_xor_sync(0xffffffffu, sq, off);

    __shared__ float red[4];
    __shared__ float sv[HD];
    if ((d & 31) == 0) red[d >> 5] = sq;
    __syncthreads();
    float mean = (red[0] + red[1] + red[2] + red[3]) * (1.0f / 128.0f);
    float nv = w[d] * (v * rsqrtf(mean + 1e-6f));
    sv[d] = nv;
    __syncthreads();

    float other = (d < 64) ? -sv[d + 64] : sv[d - 64];
    float ang = (float)((double)s * g_invfreq[d & 63]);
    float c, sn;
    sincosf(ang, &sn, &c);
    base[d] = cvt_tf32((nv * c + other * sn) * scale);
}

// ---------------- V pre-transpose: g_v[S,KV,D] -> g_vt[KV,D,S] (tf32) -------
__global__ __launch_bounds__(256) void transpose_v(const float* __restrict__ V,
                                                   float* __restrict__ Vt)
{
    __shared__ float tl[128][65];
    const int s0 = blockIdx.x * 64, kv = blockIdx.y, t = threadIdx.x;
    #pragma unroll
    for (int w = 0; w < 32; w++) {
        int idx = t + w * 256;
        int sl = idx >> 7, d = idx & 127;
        tl[d][sl] = cvt_tf32(V[((size_t)(s0 + sl) * NKV + kv) * HD + d]);
    }
    __syncthreads();
    #pragma unroll
    for (int w = 0; w < 32; w++) {
        int idx = t + w * 256;
        int d = idx >> 6, sp = idx & 63;
        int g = sp & 56;
        int p = sp & 7;
        int slog = g + ((p < 4) ? 2 * p : 2 * p - 7);
        Vt[((size_t)kv * HD + d) * SEQ + s0 + sp] = tl[d][slog];
    }
}

// ================= causal flash attention on tf32 mma =======================
#define ATT_KST   65536
#define ATT_STAGE 67584
#define ATT_SMEM  200704

__global__ __launch_bounds__(256) void attn_mma(const float* __restrict__ Qg,
                                                const float* __restrict__ Kg,
                                                const float* __restrict__ Vtg,
                                                float* __restrict__ Og)
{
    extern __shared__ char sm[];
    const uint32_t smb = smem_u32(sm);
    const int t = threadIdx.x, lane = t & 31, wid = t >> 5;
    const int qb = (int)gridDim.x - 1 - (int)blockIdx.x;   // LPT: heavy first
    const int h = blockIdx.y, kvh = h >> 2;
    const int q0 = qb * 128;
    const int wbase = wid * 16;

    #pragma unroll
    for (int u = 0; u < 16; u++) {
        int idx = t + u * 256;
        int row = idx >> 5, col = (idx & 31) * 4;
        float4 v = *(const float4*)&Qg[((size_t)(q0 + row) * NH + h) * HD + col];
        *(float4*)(sm + SWQ((uint32_t)(row * 512 + col * 4))) = v;
    }

    float o[16][4];
    #pragma unroll
    for (int i = 0; i < 16; i++)
        #pragma unroll
        for (int x = 0; x < 4; x++) o[i][x] = 0.0f;
    float m0 = -1e30f, m1 = -1e30f, l0 = 0.0f, l1 = 0.0f;

    const int lr8 = lane & 7;
    const uint32_t qa_row = (uint32_t)((wbase + lr8 + ((lane & 8) ? 8 : 0)) * 512
                                       + ((lane & 16) ? 16 : 0));
    uint32_t kb_row[4];
    #pragma unroll
    for (int hh = 0; hh < 4; hh++)
        kb_row[hh] = (uint32_t)((hh * 16 + lr8 + ((lane & 16) ? 8 : 0)) * 512
                                + ((lane & 8) ? 16 : 0));
    uint32_t vb_row[8];
    #pragma unroll
    for (int hh = 0; hh < 8; hh++)
        vb_row[hh] = (uint32_t)((hh * 16 + lr8 + ((lane & 16) ? 8 : 0)) * 272
                                + ((lane & 8) ? 16 : 0));

    const int nkt = 2 * qb + 2;
    const float* kbase_g = Kg + (size_t)kvh * HD;
    const float* vbase_g = Vtg + (size_t)kvh * HD * SEQ;

    auto issue_tile = [&](int kt2, int stg) {
        const uint32_t kb = smb + ATT_KST + (uint32_t)stg * ATT_STAGE;
        const uint32_t vb = kb + 32768;
        #pragma unroll
        for (int u = 0; u < 8; u++) {
            int idx = t + u * 256;
            int r = idx >> 5, c = idx & 31;
            uint32_t dst = kb + SWQ((uint32_t)(r * 512 + c * 16));
            const void* src = (const char*)(kbase_g + (size_t)(kt2 * 64 + r) * NKV * HD) + c * 16;
            CP_ASYNC16(dst, src);
        }
        #pragma unroll
        for (int u = 0; u < 8; u++) {
            int idx = t + u * 256;
            int dd = idx >> 4, c = idx & 15;
            uint32_t dst = vb + (uint32_t)(dd * 272 + c * 16);
            const void* src = (const char*)(vbase_g + (size_t)dd * SEQ + kt2 * 64) + c * 16;
            CP_ASYNC16(dst, src);
        }
    };

    issue_tile(0, 0);
    CP_COMMIT();

    for (int kt = 0; kt < nkt; kt++) {
        if (kt + 1 < nkt) {
            issue_tile(kt + 1, (kt + 1) & 1);
            CP_COMMIT();
            CP_WAIT1();
        } else {
            CP_WAIT0();
        }
        __syncthreads();

        const uint32_t sK = smb + ATT_KST + (uint32_t)(kt & 1) * ATT_STAGE;
        const uint32_t sV = sK + 32768;

        const bool skip = (kt == 2 * qb + 1) && (wid < 4);
        const bool needmask = (kt >= 2 * qb);

        if (!skip) {
            float s[8][4];
            #pragma unroll
            for (int i = 0; i < 8; i++)
                #pragma unroll
                for (int x = 0; x < 4; x++) s[i][x] = 0.0f;

            #pragma unroll
            for (int ks = 0; ks < 16; ks++) {
                uint32_t a[4], b[4][4];
                LDSM_X4(a[0], a[1], a[2], a[3], smb + SWQ(qa_row + ks * 32));
                #pragma unroll
                for (int hh = 0; hh < 4; hh++)
                    LDSM_X4(b[hh][0], b[hh][1], b[hh][2], b[hh][3],
                            sK + SWQ(kb_row[hh] + ks * 32));
                #pragma unroll
                for (int nt = 0; nt < 8; nt++)
                    MMA_TF32(s[nt], a[0], a[1], a[2], a[3],
                             b[nt >> 1][(nt & 1) * 2], b[nt >> 1][(nt & 1) * 2 + 1]);
            }

            if (needmask) {
                const int r0 = q0 + wbase + (lane >> 2);
                #pragma unroll
                for (int nt = 0; nt < 8; nt++) {
                    int cbase = kt * 64 + nt * 8 + 2 * (lane & 3);
                    if (cbase > r0)         s[nt][0] = -1e30f;
                    if (cbase + 1 > r0)     s[nt][1] = -1e30f;
                    if (cbase > r0 + 8)     s[nt][2] = -1e30f;
                    if (cbase + 1 > r0 + 8) s[nt][3] = -1e30f;
                }
            }

            float mx0 = -1e30f, mx1 = -1e30f;
            #pragma unroll
            for (int nt = 0; nt < 8; nt++) {
                mx0 = fmaxf(mx0, fmaxf(s[nt][0], s[nt][1]));
                mx1 = fmaxf(mx1, fmaxf(s[nt][2], s[nt][3]));
            }
            mx0 = fmaxf(mx0, __shfl_xor_sync(0xffffffffu, mx0, 1));
            mx0 = fmaxf(mx0, __shfl_xor_sync(0xffffffffu, mx0, 2));
            mx1 = fmaxf(mx1, __shfl_xor_sync(0xffffffffu, mx1, 1));
            mx1 = fmaxf(mx1, __shfl_xor_sync(0xffffffffu, mx1, 2));
            float mn0 = fmaxf(m0, mx0), mn1 = fmaxf(m1, mx1);
            float al0 = __expf(m0 - mn0), al1 = __expf(m1 - mn1);
            m0 = mn0; m1 = mn1;
            float ls0 = 0.0f, ls1 = 0.0f;
            #pragma unroll
            for (int nt = 0; nt < 8; nt++) {
                s[nt][0] = __expf(s[nt][0] - mn0);
                s[nt][1] = __expf(s[nt][1] - mn0);
                s[nt][2] = __expf(s[nt][2] - mn1);
                s[nt][3] = __expf(s[nt][3] - mn1);
                ls0 += s[nt][0] + s[nt][1];
                ls1 += s[nt][2] + s[nt][3];
            }
            ls0 += __shfl_xor_sync(0xffffffffu, ls0, 1);
            ls0 += __shfl_xor_sync(0xffffffffu, ls0, 2);
            ls1 += __shfl_xor_sync(0xffffffffu, ls1, 1);
            ls1 += __shfl_xor_sync(0xffffffffu, ls1, 2);
            l0 = l0 * al0 + ls0;
            l1 = l1 * al1 + ls1;
            #pragma unroll
            for (int i = 0; i < 16; i++) {
                o[i][0] *= al0; o[i][1] *= al0;
                o[i][2] *= al1; o[i][3] *= al1;
            }

            #pragma unroll
            for (int ks = 0; ks < 8; ks++) {
                uint32_t pa0 = cvt_tf32_bits(s[ks][0]);
                uint32_t pa1 = cvt_tf32_bits(s[ks][2]);
                uint32_t pa2 = cvt_tf32_bits(s[ks][1]);
                uint32_t pa3 = cvt_tf32_bits(s[ks][3]);
                #pragma unroll
                for (int hh = 0; hh < 8; hh++) {
                    uint32_t b[4];
                    LDSM_X4(b[0], b[1], b[2], b[3], sV + vb_row[hh] + ks * 32);
                    MMA_TF32(o[2 * hh],     pa0, pa1, pa2, pa3, b[0], b[1]);
                    MMA_TF32(o[2 * hh + 1], pa0, pa1, pa2, pa3, b[2], b[3]);
                }
            }
        }
        __syncthreads();
    }

    const float i0 = 1.0f / l0, i1 = 1.0f / l1;
    const int row = q0 + wbase + (lane >> 2);
    const int colb = 2 * (lane & 3);
    #pragma unroll
    for (int nt = 0; nt < 16; nt++) {
        float* p0 = Og + ((size_t)row * NH + h) * HD + nt * 8 + colb;
        *(float2*)p0 = make_float2(cvt_tf32(o[nt][0] * i0), cvt_tf32(o[nt][1] * i0));
        float* p1 = Og + ((size_t)(row + 8) * NH + h) * HD + nt * 8 + colb;
        *(float2*)p1 = make_float2(cvt_tf32(o[nt][2] * i1), cvt_tf32(o[nt][3] * i1));
    }
}

// ---------------- launch -----------------------------------------------------
extern "C" void kernel_launch(void* const* d_in, const int* in_sizes, int n_in,
                              void* d_out, int out_size)
{
    const float* x  = (const float*)d_in[0];
    const float* Wq = (const float*)d_in[3];
    const float* Wk = (const float*)d_in[4];
    const float* Wv = (const float*)d_in[5];
    const float* Wo = (const float*)d_in[6];
    const float* qw = (const float*)d_in[7];
    const float* kw = (const float*)d_in[8];
    float* out = (float*)d_out;

    void* p;
    cudaGetSymbolAddress(&p, g_q);   float* gq  = (float*)p;
    cudaGetSymbolAddress(&p, g_k);   float* gk  = (float*)p;
    cudaGetSymbolAddress(&p, g_v);   float* gv  = (float*)p;
    cudaGetSymbolAddress(&p, g_vt);  float* gvt = (float*)p;
    cudaGetSymbolAddress(&p, g_ctx); float* gc  = (float*)p;
    cudaGetSymbolAddress(&p, g_xt);  float* gxt = (float*)p;
    cudaGetSymbolAddress(&p, g_wq);  float* gwq = (float*)p;
    cudaGetSymbolAddress(&p, g_wk);  float* gwk = (float*)p;
    cudaGetSymbolAddress(&p, g_wv);  float* gwv = (float*)p;
    cudaGetSymbolAddress(&p, g_wo);  float* gwo = (float*)p;

    cudaFuncSetAttribute(gemm_mma, cudaFuncAttributeMaxDynamicSharedMemorySize, GSM_TOTAL);
    cudaFuncSetAttribute(attn_mma, cudaFuncAttributeMaxDynamicSharedMemorySize, ATT_SMEM);

    init_invfreq_kernel<<<1, 64>>>();

    // pre-convert all GEMM operands to tf32
    cvt_tf32_kernel<<<(SEQ * HIDDEN / 4 + 255) / 256, 256>>>(x, gxt, SEQ * HIDDEN / 4);
    cvt_tf32_kernel<<<(NH * HD * HIDDEN / 4 + 255) / 256, 256>>>(Wq, gwq, NH * HD * HIDDEN / 4);
    cvt_tf32_kernel<<<(NKV * HD * HIDDEN / 4 + 255) / 256, 256>>>(Wk, gwk, NKV * HD * HIDDEN / 4);
    cvt_tf32_kernel<<<(NKV * HD * HIDDEN / 4 + 255) / 256, 256>>>(Wv, gwv, NKV * HD * HIDDEN / 4);
    cvt_tf32_kernel<<<(HIDDEN * NH * HD / 4 + 255) / 256, 256>>>(Wo, gwo, HIDDEN * NH * HD / 4);

    gemm_mma<<<dim3(HIDDEN / 128, SEQ / 128), 256, GSM_TOTAL>>>(gxt, gwq, gq, SEQ, NH * HD, HIDDEN);
    gemm_mma<<<dim3((NKV * HD) / 128, SEQ / 128), 256, GSM_TOTAL>>>(gxt, gwk, gk, SEQ, NKV * HD, HIDDEN);
    gemm_mma<<<dim3((NKV * HD) / 128, SEQ / 128), 256, GSM_TOTAL>>>(gxt, gwv, gv, SEQ, NKV * HD, HIDDEN);

    transpose_v<<<dim3(SEQ / 64, NKV), 256>>>(gv, gvt);

    rmsnorm_rope_kernel<<<dim3(SEQ, NH), 128>>>(gq, qw, NH, 0.08838834764831845f);
    rmsnorm_rope_kernel<<<dim3(SEQ, NKV), 128>>>(gk, kw, NKV, 1.0f);

    attn_mma<<<dim3(SEQ / 128, NH), 256, ATT_SMEM>>>(gq, gk, gvt, gc);

    gemm_mma<<<dim3(HIDDEN / 128, SEQ / 128), 256, GSM_TOTAL>>>(gc, gwo, out, SEQ, HIDDEN, HIDDEN);
}